// round 2
// baseline (speedup 1.0000x reference)
#include <cuda_runtime.h>
#include <math.h>
#include <cfloat>

#define T_TOK 2048
#define HID   2048
#define NE_OLD 128
#define NE     48
#define TOPK   8
#define INTER  768
#define CAPCT  768

// ---------------- scratch (device globals; no allocation allowed) ----------
__device__ float d_logits[T_TOK * NE_OLD];
__device__ int   d_counts[NE];
__device__ int   d_slot_token[NE * CAPCT];
__device__ int   d_sel_idx[T_TOK * TOPK];
__device__ float d_sel_w[T_TOK * TOPK];
__device__ float d_hbuf[(size_t)NE * CAPCT * INTER];   // 113 MB
__device__ float d_ybuf[(size_t)NE * CAPCT * HID];     // 302 MB

// ---------------- 1) gating logits: C[t,e] = x[t,:] . gw[e,:] -------------
// tile 32x32, K chunks of 32, 256 threads, 2x2 per thread
__global__ void __launch_bounds__(256) gating_kernel(const float* __restrict__ x,
                                                     const float* __restrict__ gw)
{
    __shared__ float Xs[32][33];
    __shared__ float Gs[32][33];
    int tid = threadIdx.x;
    if (blockIdx.x == 0 && blockIdx.y == 0 && tid < NE) d_counts[tid] = 0;

    int t0 = blockIdx.x * 32;
    int e0 = blockIdx.y * 32;
    int ty = tid / 16, tx = tid % 16;

    int lr = tid >> 3;          // 0..31 (row)
    int lk = (tid & 7) * 4;     // 0..28 (k offset)

    float acc00 = 0.f, acc01 = 0.f, acc10 = 0.f, acc11 = 0.f;

    for (int k0 = 0; k0 < HID; k0 += 32) {
        float4 xv = *(const float4*)&x[(size_t)(t0 + lr) * HID + k0 + lk];
        float4 gv = *(const float4*)&gw[(size_t)(e0 + lr) * HID + k0 + lk];
        __syncthreads();
        Xs[lk + 0][lr] = xv.x; Xs[lk + 1][lr] = xv.y; Xs[lk + 2][lr] = xv.z; Xs[lk + 3][lr] = xv.w;
        Gs[lk + 0][lr] = gv.x; Gs[lk + 1][lr] = gv.y; Gs[lk + 2][lr] = gv.z; Gs[lk + 3][lr] = gv.w;
        __syncthreads();
#pragma unroll
        for (int k = 0; k < 32; k++) {
            float a0 = Xs[k][ty * 2], a1 = Xs[k][ty * 2 + 1];
            float b0 = Gs[k][tx * 2], b1 = Gs[k][tx * 2 + 1];
            acc00 += a0 * b0; acc01 += a0 * b1;
            acc10 += a1 * b0; acc11 += a1 * b1;
        }
    }
    int t = t0 + ty * 2, e = e0 + tx * 2;
    d_logits[(size_t)(t + 0) * NE_OLD + e + 0] = acc00;
    d_logits[(size_t)(t + 0) * NE_OLD + e + 1] = acc01;
    d_logits[(size_t)(t + 1) * NE_OLD + e + 0] = acc10;
    d_logits[(size_t)(t + 1) * NE_OLD + e + 1] = acc11;
}

// ---------------- 2) routing: top-8 + softmax over selected + capacity ----
// one warp per token; 8 warps per block
__global__ void __launch_bounds__(256) routing_kernel(const int* __restrict__ o2n)
{
    int warp = threadIdx.x >> 5;
    int lane = threadIdx.x & 31;
    int token = blockIdx.x * 8 + warp;

    float v[4];
#pragma unroll
    for (int j = 0; j < 4; j++) {
        int ee = lane + j * 32;
        float lv = d_logits[(size_t)token * NE_OLD + ee];
        v[j] = (o2n[ee] >= 0) ? lv : -FLT_MAX;
    }

    float topv[TOPK];
    int   tope[TOPK];
#pragma unroll
    for (int it = 0; it < TOPK; it++) {
        float bv = v[0]; int be = lane;
#pragma unroll
        for (int j = 1; j < 4; j++) {
            int ee = lane + j * 32;
            if (v[j] > bv || (v[j] == bv && ee < be)) { bv = v[j]; be = ee; }
        }
#pragma unroll
        for (int off = 16; off; off >>= 1) {
            float ov = __shfl_xor_sync(0xffffffffu, bv, off);
            int   oe = __shfl_xor_sync(0xffffffffu, be, off);
            if (ov > bv || (ov == bv && oe < be)) { bv = ov; be = oe; }
        }
        topv[it] = bv; tope[it] = be;
        int wj = be >> 5;
#pragma unroll
        for (int j = 0; j < 4; j++)
            if (wj == j && (be & 31) == lane) v[j] = -FLT_MAX;
    }

    // softmax over the 8 selected logits (== renormalized top-8 of softmax)
    float m = topv[0];
    float w[TOPK];
    float s = 0.f;
#pragma unroll
    for (int i = 0; i < TOPK; i++) { w[i] = expf(topv[i] - m); s += w[i]; }
    float inv = 1.f / s;

    if (lane < TOPK) {
        int i = lane;
        float wi = 0.f;
        int enew = 0;
#pragma unroll
        for (int j = 0; j < TOPK; j++) if (j == i) { wi = w[j] * inv; enew = o2n[tope[j]]; }
        int pos = atomicAdd(&d_counts[enew], 1);
        int sidx = 0; float sw = 0.f;
        if (pos < CAPCT) {
            d_slot_token[enew * CAPCT + pos] = token;
            sidx = enew * CAPCT + pos;
            sw = wi;
        }
        d_sel_idx[token * TOPK + i] = sidx;
        d_sel_w[token * TOPK + i] = sw;
    }
}

// ---------------- 3) GEMM1 + SiLU: h = silu(Xe @ Wg^T) * (Xe @ Wu^T) ------
// tile M=128 x N=64 (of h); computes both g and u tiles. K=2048 in chunks of 32.
__global__ void __launch_bounds__(256) gemm1_kernel(const float* __restrict__ x,
                                                    const float* __restrict__ gup)
{
    __shared__ float As[32][132];
    __shared__ float Bgs[32][68];
    __shared__ float Bus[32][68];
    __shared__ int toks[128];

    int e = blockIdx.z;
    int cnt = min(d_counts[e], CAPCT);
    int m0 = blockIdx.y * 128;
    if (m0 >= cnt) return;
    int n0 = blockIdx.x * 64;
    int tid = threadIdx.x;

    if (tid < 128) {
        int m = m0 + tid;
        toks[tid] = d_slot_token[e * CAPCT + ((m < cnt) ? m : 0)];
    }
    __syncthreads();

    const float* Bg = gup + (size_t)e * 1536 * HID + (size_t)n0 * HID;
    const float* Bu = Bg + (size_t)768 * HID;

    float accg[8][4]; float accu[8][4];
#pragma unroll
    for (int i = 0; i < 8; i++)
#pragma unroll
        for (int j = 0; j < 4; j++) { accg[i][j] = 0.f; accu[i][j] = 0.f; }

    int ty = tid / 16, tx = tid % 16;

    // loader lanes
    int ar[4], ak[4];
#pragma unroll
    for (int i = 0; i < 4; i++) { int q = tid + i * 256; ar[i] = q >> 3; ak[i] = (q & 7) * 4; }
    int br[2], bk[2];
#pragma unroll
    for (int i = 0; i < 2; i++) { int q = tid + i * 256; br[i] = q >> 3; bk[i] = (q & 7) * 4; }

    int atok[4];
#pragma unroll
    for (int i = 0; i < 4; i++) atok[i] = toks[ar[i]];

    for (int k0 = 0; k0 < HID; k0 += 32) {
        float4 av[4], bgv[2], buv[2];
#pragma unroll
        for (int i = 0; i < 4; i++)
            av[i] = *(const float4*)&x[(size_t)atok[i] * HID + k0 + ak[i]];
#pragma unroll
        for (int i = 0; i < 2; i++) {
            bgv[i] = *(const float4*)&Bg[(size_t)br[i] * HID + k0 + bk[i]];
            buv[i] = *(const float4*)&Bu[(size_t)br[i] * HID + k0 + bk[i]];
        }
        __syncthreads();
#pragma unroll
        for (int i = 0; i < 4; i++) {
            As[ak[i] + 0][ar[i]] = av[i].x; As[ak[i] + 1][ar[i]] = av[i].y;
            As[ak[i] + 2][ar[i]] = av[i].z; As[ak[i] + 3][ar[i]] = av[i].w;
        }
#pragma unroll
        for (int i = 0; i < 2; i++) {
            Bgs[bk[i] + 0][br[i]] = bgv[i].x; Bgs[bk[i] + 1][br[i]] = bgv[i].y;
            Bgs[bk[i] + 2][br[i]] = bgv[i].z; Bgs[bk[i] + 3][br[i]] = bgv[i].w;
            Bus[bk[i] + 0][br[i]] = buv[i].x; Bus[bk[i] + 1][br[i]] = buv[i].y;
            Bus[bk[i] + 2][br[i]] = buv[i].z; Bus[bk[i] + 3][br[i]] = buv[i].w;
        }
        __syncthreads();
#pragma unroll
        for (int k = 0; k < 32; k++) {
            const float4* ap = (const float4*)&As[k][ty * 8];
            float4 a0 = ap[0], a1 = ap[1];
            float4 bg = *(const float4*)&Bgs[k][tx * 4];
            float4 bu = *(const float4*)&Bus[k][tx * 4];
            float a[8] = {a0.x, a0.y, a0.z, a0.w, a1.x, a1.y, a1.z, a1.w};
            float g4[4] = {bg.x, bg.y, bg.z, bg.w};
            float u4[4] = {bu.x, bu.y, bu.z, bu.w};
#pragma unroll
            for (int mi = 0; mi < 8; mi++)
#pragma unroll
                for (int nj = 0; nj < 4; nj++) {
                    accg[mi][nj] += a[mi] * g4[nj];
                    accu[mi][nj] += a[mi] * u4[nj];
                }
        }
    }

#pragma unroll
    for (int mi = 0; mi < 8; mi++) {
        int m = m0 + ty * 8 + mi;
        if (m < cnt) {
            float4 hv;
            float g;
            g = accg[mi][0]; hv.x = g / (1.f + __expf(-g)) * accu[mi][0];
            g = accg[mi][1]; hv.y = g / (1.f + __expf(-g)) * accu[mi][1];
            g = accg[mi][2]; hv.z = g / (1.f + __expf(-g)) * accu[mi][2];
            g = accg[mi][3]; hv.w = g / (1.f + __expf(-g)) * accu[mi][3];
            *(float4*)&d_hbuf[((size_t)e * CAPCT + m) * INTER + n0 + tx * 4] = hv;
        }
    }
}

// ---------------- 4) GEMM2: y = h @ down^T -> ybuf ------------------------
// tile 128x128, thread 8x8, K=768 in chunks of 16
__global__ void __launch_bounds__(256) gemm2_kernel(const float* __restrict__ down)
{
    __shared__ float As[16][132];
    __shared__ float Bs[16][132];

    int e = blockIdx.z;
    int cnt = min(d_counts[e], CAPCT);
    int m0 = blockIdx.y * 128;
    if (m0 >= cnt) return;
    int n0 = blockIdx.x * 128;
    int tid = threadIdx.x;

    const float* A = d_hbuf + (size_t)e * CAPCT * INTER;
    const float* B = down + (size_t)e * HID * INTER + (size_t)n0 * INTER;

    float acc[8][8];
#pragma unroll
    for (int i = 0; i < 8; i++)
#pragma unroll
        for (int j = 0; j < 8; j++) acc[i][j] = 0.f;

    int ty = tid / 16, tx = tid % 16;
    int lr[2], lk[2];
#pragma unroll
    for (int i = 0; i < 2; i++) { int q = tid + i * 256; lr[i] = q >> 2; lk[i] = (q & 3) * 4; }

    for (int k0 = 0; k0 < INTER; k0 += 16) {
        float4 av[2], bv[2];
#pragma unroll
        for (int i = 0; i < 2; i++) {
            av[i] = *(const float4*)&A[(size_t)(m0 + lr[i]) * INTER + k0 + lk[i]];
            bv[i] = *(const float4*)&B[(size_t)lr[i] * INTER + k0 + lk[i]];
        }
        __syncthreads();
#pragma unroll
        for (int i = 0; i < 2; i++) {
            As[lk[i] + 0][lr[i]] = av[i].x; As[lk[i] + 1][lr[i]] = av[i].y;
            As[lk[i] + 2][lr[i]] = av[i].z; As[lk[i] + 3][lr[i]] = av[i].w;
            Bs[lk[i] + 0][lr[i]] = bv[i].x; Bs[lk[i] + 1][lr[i]] = bv[i].y;
            Bs[lk[i] + 2][lr[i]] = bv[i].z; Bs[lk[i] + 3][lr[i]] = bv[i].w;
        }
        __syncthreads();
#pragma unroll
        for (int k = 0; k < 16; k++) {
            const float4* ap = (const float4*)&As[k][ty * 8];
            const float4* bp = (const float4*)&Bs[k][tx * 8];
            float4 a0 = ap[0], a1 = ap[1];
            float4 b0 = bp[0], b1 = bp[1];
            float a[8] = {a0.x, a0.y, a0.z, a0.w, a1.x, a1.y, a1.z, a1.w};
            float b[8] = {b0.x, b0.y, b0.z, b0.w, b1.x, b1.y, b1.z, b1.w};
#pragma unroll
            for (int mi = 0; mi < 8; mi++)
#pragma unroll
                for (int nj = 0; nj < 8; nj++)
                    acc[mi][nj] += a[mi] * b[nj];
        }
    }

#pragma unroll
    for (int mi = 0; mi < 8; mi++) {
        int m = m0 + ty * 8 + mi;
        if (m < cnt) {
            float* yp = &d_ybuf[((size_t)e * CAPCT + m) * HID + n0 + tx * 8];
            float4 v0 = {acc[mi][0], acc[mi][1], acc[mi][2], acc[mi][3]};
            float4 v1 = {acc[mi][4], acc[mi][5], acc[mi][6], acc[mi][7]};
            *(float4*)(yp + 0) = v0;
            *(float4*)(yp + 4) = v1;
        }
    }
}

// ---------------- 5) combine: out[t] = sum_k w_k * ybuf[sel_k] ------------
__global__ void __launch_bounds__(256) gather_kernel(float* __restrict__ out)
{
    int t = blockIdx.x;
    __shared__ int  sidx[TOPK];
    __shared__ float sw[TOPK];
    if (threadIdx.x < TOPK) {
        sidx[threadIdx.x] = d_sel_idx[t * TOPK + threadIdx.x];
        sw[threadIdx.x]   = d_sel_w[t * TOPK + threadIdx.x];
    }
    __syncthreads();

    const float4* yb = (const float4*)d_ybuf;
    float4* o = (float4*)(out + (size_t)t * HID);
#pragma unroll
    for (int v = threadIdx.x; v < HID / 4; v += 256) {
        float4 acc = {0.f, 0.f, 0.f, 0.f};
#pragma unroll
        for (int k = 0; k < TOPK; k++) {
            float4 yv = yb[(size_t)sidx[k] * (HID / 4) + v];
            float wk = sw[k];
            acc.x += wk * yv.x; acc.y += wk * yv.y;
            acc.z += wk * yv.z; acc.w += wk * yv.w;
        }
        o[v] = acc;
    }
}

// ---------------- launch ---------------------------------------------------
extern "C" void kernel_launch(void* const* d_in, const int* in_sizes, int n_in,
                              void* d_out, int out_size)
{
    const float* x    = (const float*)d_in[0];   // hidden_states [2,1024,2048]
    const float* gw   = (const float*)d_in[1];   // gate_weight [128,2048]
    const float* gup  = (const float*)d_in[2];   // gate_up_proj [48,1536,2048]
    const float* down = (const float*)d_in[3];   // down_proj [48,2048,768]
    const int*   o2n  = (const int*)d_in[4];     // old_to_new [128]

    gating_kernel<<<dim3(T_TOK / 32, NE_OLD / 32), 256>>>(x, gw);
    routing_kernel<<<T_TOK / 8, 256>>>(o2n);
    gemm1_kernel<<<dim3(INTER / 64, CAPCT / 128, NE), 256>>>(x, gup);
    gemm2_kernel<<<dim3(HID / 128, CAPCT / 128, NE), 256>>>(down);
    gather_kernel<<<T_TOK, 256>>>((float*)d_out);
}

// round 6
// speedup vs baseline: 2.7177x; 2.7177x over previous
#include <cuda_runtime.h>
#include <math.h>
#include <cfloat>
#include <stdint.h>

#define T_TOK 2048
#define HID   2048
#define NE_OLD 128
#define NE     48
#define TOPK   8
#define INTER  768
#define CAPCT  768

// ---------------- scratch (device globals; no allocation allowed) ----------
__device__ float d_logits[T_TOK * NE_OLD];
__device__ int   d_counts[NE];
__device__ int   d_slot_token[NE * CAPCT];
__device__ int   d_sel_idx[T_TOK * TOPK];
__device__ float d_sel_w[T_TOK * TOPK];
__device__ float d_hbuf[(size_t)NE * CAPCT * INTER];   // 113 MB
__device__ float d_ybuf[(size_t)NE * CAPCT * HID];     // 302 MB

// ======================= mma helpers (plain sm_103-legal) ==================
__device__ __forceinline__ uint32_t f2tf32(float f) {
    uint32_t r;
    asm("cvt.rna.tf32.f32 %0, %1;" : "=r"(r) : "f"(f));
    return r;
}
__device__ __forceinline__ void mma_tf32(float* c, const uint32_t* a, const uint32_t* b) {
    asm volatile(
        "mma.sync.aligned.m16n8k8.row.col.f32.tf32.tf32.f32 "
        "{%0,%1,%2,%3}, {%4,%5,%6,%7}, {%8,%9}, {%0,%1,%2,%3};"
        : "+f"(c[0]), "+f"(c[1]), "+f"(c[2]), "+f"(c[3])
        : "r"(a[0]), "r"(a[1]), "r"(a[2]), "r"(a[3]), "r"(b[0]), "r"(b[1]));
}

#define KC 32          // K chunk per smem stage
#define SPAD 36        // 32 + 4 pad floats: bank = (4*row+q) mod 32, conflict-free

// ---------------- 1) gating logits (fp32 exact — selection must be stable) -
__global__ void __launch_bounds__(256) gating_kernel(const float* __restrict__ x,
                                                     const float* __restrict__ gw)
{
    __shared__ float Xs[32][33];
    __shared__ float Gs[32][33];
    int tid = threadIdx.x;
    if (blockIdx.x == 0 && blockIdx.y == 0 && tid < NE) d_counts[tid] = 0;

    int t0 = blockIdx.x * 32;
    int e0 = blockIdx.y * 32;
    int ty = tid / 16, tx = tid % 16;
    int lr = tid >> 3;
    int lk = (tid & 7) * 4;

    float acc00 = 0.f, acc01 = 0.f, acc10 = 0.f, acc11 = 0.f;

    for (int k0 = 0; k0 < HID; k0 += 32) {
        float4 xv = *(const float4*)&x[(size_t)(t0 + lr) * HID + k0 + lk];
        float4 gv = *(const float4*)&gw[(size_t)(e0 + lr) * HID + k0 + lk];
        __syncthreads();
        Xs[lk + 0][lr] = xv.x; Xs[lk + 1][lr] = xv.y; Xs[lk + 2][lr] = xv.z; Xs[lk + 3][lr] = xv.w;
        Gs[lk + 0][lr] = gv.x; Gs[lk + 1][lr] = gv.y; Gs[lk + 2][lr] = gv.z; Gs[lk + 3][lr] = gv.w;
        __syncthreads();
#pragma unroll
        for (int k = 0; k < 32; k++) {
            float a0 = Xs[k][ty * 2], a1 = Xs[k][ty * 2 + 1];
            float b0 = Gs[k][tx * 2], b1 = Gs[k][tx * 2 + 1];
            acc00 += a0 * b0; acc01 += a0 * b1;
            acc10 += a1 * b0; acc11 += a1 * b1;
        }
    }
    int t = t0 + ty * 2, e = e0 + tx * 2;
    d_logits[(size_t)(t + 0) * NE_OLD + e + 0] = acc00;
    d_logits[(size_t)(t + 0) * NE_OLD + e + 1] = acc01;
    d_logits[(size_t)(t + 1) * NE_OLD + e + 0] = acc10;
    d_logits[(size_t)(t + 1) * NE_OLD + e + 1] = acc11;
}

// ---------------- 2) routing ----------------------------------------------
__global__ void __launch_bounds__(256) routing_kernel(const int* __restrict__ o2n)
{
    int warp = threadIdx.x >> 5;
    int lane = threadIdx.x & 31;
    int token = blockIdx.x * 8 + warp;

    float v[4];
#pragma unroll
    for (int j = 0; j < 4; j++) {
        int ee = lane + j * 32;
        float lv = d_logits[(size_t)token * NE_OLD + ee];
        v[j] = (o2n[ee] >= 0) ? lv : -FLT_MAX;
    }

    float topv[TOPK];
    int   tope[TOPK];
#pragma unroll
    for (int it = 0; it < TOPK; it++) {
        float bv = v[0]; int be = lane;
#pragma unroll
        for (int j = 1; j < 4; j++) {
            int ee = lane + j * 32;
            if (v[j] > bv || (v[j] == bv && ee < be)) { bv = v[j]; be = ee; }
        }
#pragma unroll
        for (int off = 16; off; off >>= 1) {
            float ov = __shfl_xor_sync(0xffffffffu, bv, off);
            int   oe = __shfl_xor_sync(0xffffffffu, be, off);
            if (ov > bv || (ov == bv && oe < be)) { bv = ov; be = oe; }
        }
        topv[it] = bv; tope[it] = be;
        int wj = be >> 5;
#pragma unroll
        for (int j = 0; j < 4; j++)
            if (wj == j && (be & 31) == lane) v[j] = -FLT_MAX;
    }

    float m = topv[0];
    float w[TOPK];
    float s = 0.f;
#pragma unroll
    for (int i = 0; i < TOPK; i++) { w[i] = expf(topv[i] - m); s += w[i]; }
    float inv = 1.f / s;

    if (lane < TOPK) {
        int i = lane;
        float wi = 0.f;
        int enew = 0;
#pragma unroll
        for (int j = 0; j < TOPK; j++) if (j == i) { wi = w[j] * inv; enew = o2n[tope[j]]; }
        int pos = atomicAdd(&d_counts[enew], 1);
        int sidx = 0; float sw = 0.f;
        if (pos < CAPCT) {
            d_slot_token[enew * CAPCT + pos] = token;
            sidx = enew * CAPCT + pos;
            sw = wi;
        }
        d_sel_idx[token * TOPK + i] = sidx;
        d_sel_w[token * TOPK + i] = sw;
    }
}

// ---------------- 3) GEMM1 (tf32 mma.sync) + fused SiLU --------------------
// Block tile: M=128 rows x 128 concat cols (16-row g/u interleave per warp).
// 8 warps as 2(M) x 4(N); warp tile 64x32 of m16n8k8 fragments.
// Warp wn's 32 cols = gate[n0+16*wn .. +16) ++ up[n0+16*wn .. +16) -> SiLU in regs.
__global__ void __launch_bounds__(256) gemm1_mma(const float* __restrict__ x,
                                                 const float* __restrict__ gup)
{
    __shared__ float As[128][SPAD];
    __shared__ float Bs[128][SPAD];
    __shared__ int toks[128];

    int e = blockIdx.z;
    int cnt = min(d_counts[e], CAPCT);
    int m0 = blockIdx.y * 128;
    if (m0 >= cnt) return;
    int n0 = blockIdx.x * 64;           // h columns covered by this block
    int tid = threadIdx.x;
    int wid = tid >> 5, lane = tid & 31;
    int wm = wid >> 2, wn = wid & 3;
    int g = lane >> 2, q = lane & 3;

    if (tid < 128) {
        int m = m0 + tid;
        toks[tid] = d_slot_token[e * CAPCT + ((m < cnt) ? m : 0)];
    }
    __syncthreads();

    // loader mapping: 1024 float4 per tile, 4 per thread
    int arow[4], aqf[4];
    const float* bsrc[4];
#pragma unroll
    for (int j = 0; j < 4; j++) {
        int idx = tid + j * 256;
        arow[j] = idx >> 3;
        aqf[j]  = (idx & 7) * 4;
        int r = arow[j];
        int w = r >> 5, l = r & 31;
        int grow = (l < 16) ? (n0 + w * 16 + l) : (768 + n0 + w * 16 + (l - 16));
        bsrc[j] = gup + (size_t)e * 1536 * HID + (size_t)grow * HID + aqf[j];
    }
    int atok[4];
#pragma unroll
    for (int j = 0; j < 4; j++) atok[j] = toks[arow[j]];

    float acc[4][4][4];
#pragma unroll
    for (int i = 0; i < 4; i++)
#pragma unroll
        for (int jn = 0; jn < 4; jn++)
#pragma unroll
            for (int c = 0; c < 4; c++) acc[i][jn][c] = 0.f;

    for (int k0 = 0; k0 < HID; k0 += KC) {
        float4 av[4], bv[4];
#pragma unroll
        for (int j = 0; j < 4; j++) {
            av[j] = *(const float4*)&x[(size_t)atok[j] * HID + k0 + aqf[j]];
            bv[j] = *(const float4*)(bsrc[j] + k0);
        }
        __syncthreads();
#pragma unroll
        for (int j = 0; j < 4; j++) {
            float* ap = &As[arow[j]][aqf[j]];
            ap[0] = __uint_as_float(f2tf32(av[j].x));
            ap[1] = __uint_as_float(f2tf32(av[j].y));
            ap[2] = __uint_as_float(f2tf32(av[j].z));
            ap[3] = __uint_as_float(f2tf32(av[j].w));
            float* bp = &Bs[arow[j]][aqf[j]];
            bp[0] = __uint_as_float(f2tf32(bv[j].x));
            bp[1] = __uint_as_float(f2tf32(bv[j].y));
            bp[2] = __uint_as_float(f2tf32(bv[j].z));
            bp[3] = __uint_as_float(f2tf32(bv[j].w));
        }
        __syncthreads();
#pragma unroll
        for (int kk = 0; kk < KC / 8; kk++) {
            int kb = kk * 8;
            uint32_t afrag[4][4], bfrag[4][2];
#pragma unroll
            for (int mf = 0; mf < 4; mf++) {
                int r = wm * 64 + mf * 16;
                afrag[mf][0] = __float_as_uint(As[r + g    ][kb + q    ]);
                afrag[mf][1] = __float_as_uint(As[r + g + 8][kb + q    ]);
                afrag[mf][2] = __float_as_uint(As[r + g    ][kb + q + 4]);
                afrag[mf][3] = __float_as_uint(As[r + g + 8][kb + q + 4]);
            }
#pragma unroll
            for (int nf = 0; nf < 4; nf++) {
                int r = wn * 32 + nf * 8 + g;
                bfrag[nf][0] = __float_as_uint(Bs[r][kb + q    ]);
                bfrag[nf][1] = __float_as_uint(Bs[r][kb + q + 4]);
            }
#pragma unroll
            for (int mf = 0; mf < 4; mf++)
#pragma unroll
                for (int nf = 0; nf < 4; nf++)
                    mma_tf32(acc[mf][nf], afrag[mf], bfrag[nf]);
        }
    }

    // epilogue: frags nf 0..1 = gate cols, nf+2 = matching up cols. SiLU in regs.
#pragma unroll
    for (int mf = 0; mf < 4; mf++) {
#pragma unroll
        for (int nf = 0; nf < 2; nf++) {
#pragma unroll
            for (int half = 0; half < 2; half++) {
                int m = m0 + wm * 64 + mf * 16 + g + half * 8;
                if (m < cnt) {
                    float g0 = acc[mf][nf][half * 2 + 0];
                    float g1 = acc[mf][nf][half * 2 + 1];
                    float u0 = acc[mf][nf + 2][half * 2 + 0];
                    float u1 = acc[mf][nf + 2][half * 2 + 1];
                    float2 h;
                    h.x = g0 / (1.f + __expf(-g0)) * u0;
                    h.y = g1 / (1.f + __expf(-g1)) * u1;
                    int col = n0 + 16 * wn + 8 * nf + 2 * q;
                    *(float2*)&d_hbuf[((size_t)e * CAPCT + m) * INTER + col] = h;
                }
            }
        }
    }
}

// ---------------- 4) GEMM2 (tf32 mma.sync): y = h @ down^T -----------------
// Block tile M=128 x N=128, K=768. Same warp layout as GEMM1.
__global__ void __launch_bounds__(256) gemm2_mma(const float* __restrict__ down)
{
    __shared__ float As[128][SPAD];
    __shared__ float Bs[128][SPAD];

    int e = blockIdx.z;
    int cnt = min(d_counts[e], CAPCT);
    int m0 = blockIdx.y * 128;
    if (m0 >= cnt) return;
    int n0 = blockIdx.x * 128;
    int tid = threadIdx.x;
    int wid = tid >> 5, lane = tid & 31;
    int wm = wid >> 2, wn = wid & 3;
    int g = lane >> 2, q = lane & 3;

    const float* A = d_hbuf + ((size_t)e * CAPCT + m0) * INTER;
    const float* B = down + (size_t)e * HID * INTER + (size_t)n0 * INTER;

    int arow[4], aqf[4];
#pragma unroll
    for (int j = 0; j < 4; j++) {
        int idx = tid + j * 256;
        arow[j] = idx >> 3;
        aqf[j]  = (idx & 7) * 4;
    }

    float acc[4][4][4];
#pragma unroll
    for (int i = 0; i < 4; i++)
#pragma unroll
        for (int jn = 0; jn < 4; jn++)
#pragma unroll
            for (int c = 0; c < 4; c++) acc[i][jn][c] = 0.f;

    for (int k0 = 0; k0 < INTER; k0 += KC) {
        float4 av[4], bv[4];
#pragma unroll
        for (int j = 0; j < 4; j++) {
            av[j] = *(const float4*)&A[(size_t)arow[j] * INTER + k0 + aqf[j]];
            bv[j] = *(const float4*)&B[(size_t)arow[j] * INTER + k0 + aqf[j]];
        }
        __syncthreads();
#pragma unroll
        for (int j = 0; j < 4; j++) {
            float* ap = &As[arow[j]][aqf[j]];
            ap[0] = __uint_as_float(f2tf32(av[j].x));
            ap[1] = __uint_as_float(f2tf32(av[j].y));
            ap[2] = __uint_as_float(f2tf32(av[j].z));
            ap[3] = __uint_as_float(f2tf32(av[j].w));
            float* bp = &Bs[arow[j]][aqf[j]];
            bp[0] = __uint_as_float(f2tf32(bv[j].x));
            bp[1] = __uint_as_float(f2tf32(bv[j].y));
            bp[2] = __uint_as_float(f2tf32(bv[j].z));
            bp[3] = __uint_as_float(f2tf32(bv[j].w));
        }
        __syncthreads();
#pragma unroll
        for (int kk = 0; kk < KC / 8; kk++) {
            int kb = kk * 8;
            uint32_t afrag[4][4], bfrag[4][2];
#pragma unroll
            for (int mf = 0; mf < 4; mf++) {
                int r = wm * 64 + mf * 16;
                afrag[mf][0] = __float_as_uint(As[r + g    ][kb + q    ]);
                afrag[mf][1] = __float_as_uint(As[r + g + 8][kb + q    ]);
                afrag[mf][2] = __float_as_uint(As[r + g    ][kb + q + 4]);
                afrag[mf][3] = __float_as_uint(As[r + g + 8][kb + q + 4]);
            }
#pragma unroll
            for (int nf = 0; nf < 4; nf++) {
                int r = wn * 32 + nf * 8 + g;
                bfrag[nf][0] = __float_as_uint(Bs[r][kb + q    ]);
                bfrag[nf][1] = __float_as_uint(Bs[r][kb + q + 4]);
            }
#pragma unroll
            for (int mf = 0; mf < 4; mf++)
#pragma unroll
                for (int nf = 0; nf < 4; nf++)
                    mma_tf32(acc[mf][nf], afrag[mf], bfrag[nf]);
        }
    }

#pragma unroll
    for (int mf = 0; mf < 4; mf++) {
#pragma unroll
        for (int nf = 0; nf < 4; nf++) {
#pragma unroll
            for (int half = 0; half < 2; half++) {
                int m = m0 + wm * 64 + mf * 16 + g + half * 8;
                if (m < cnt) {
                    float2 yv;
                    yv.x = acc[mf][nf][half * 2 + 0];
                    yv.y = acc[mf][nf][half * 2 + 1];
                    int col = n0 + 32 * wn + 8 * nf + 2 * q;
                    *(float2*)&d_ybuf[((size_t)e * CAPCT + m) * HID + col] = yv;
                }
            }
        }
    }
}

// ---------------- 5) combine ----------------------------------------------
__global__ void __launch_bounds__(256) gather_kernel(float* __restrict__ out)
{
    int t = blockIdx.x;
    __shared__ int  sidx[TOPK];
    __shared__ float sw[TOPK];
    if (threadIdx.x < TOPK) {
        sidx[threadIdx.x] = d_sel_idx[t * TOPK + threadIdx.x];
        sw[threadIdx.x]   = d_sel_w[t * TOPK + threadIdx.x];
    }
    __syncthreads();

    const float4* yb = (const float4*)d_ybuf;
    float4* o = (float4*)(out + (size_t)t * HID);
#pragma unroll
    for (int v = threadIdx.x; v < HID / 4; v += 256) {
        float4 acc = {0.f, 0.f, 0.f, 0.f};
#pragma unroll
        for (int k = 0; k < TOPK; k++) {
            float4 yv = yb[(size_t)sidx[k] * (HID / 4) + v];
            float wk = sw[k];
            acc.x += wk * yv.x; acc.y += wk * yv.y;
            acc.z += wk * yv.z; acc.w += wk * yv.w;
        }
        o[v] = acc;
    }
}

// ---------------- launch ---------------------------------------------------
extern "C" void kernel_launch(void* const* d_in, const int* in_sizes, int n_in,
                              void* d_out, int out_size)
{
    const float* x    = (const float*)d_in[0];   // hidden_states [2,1024,2048]
    const float* gw   = (const float*)d_in[1];   // gate_weight [128,2048]
    const float* gup  = (const float*)d_in[2];   // gate_up_proj [48,1536,2048]
    const float* down = (const float*)d_in[3];   // down_proj [48,2048,768]
    const int*   o2n  = (const int*)d_in[4];     // old_to_new [128]

    gating_kernel<<<dim3(T_TOK / 32, NE_OLD / 32), 256>>>(x, gw);
    routing_kernel<<<T_TOK / 8, 256>>>(o2n);
    gemm1_mma<<<dim3(INTER / 64, CAPCT / 128, NE), 256>>>(x, gup);
    gemm2_mma<<<dim3(HID / 128, CAPCT / 128, NE), 256>>>(down);
    gather_kernel<<<T_TOK, 256>>>((float*)d_out);
}

// round 9
// speedup vs baseline: 2.9035x; 1.0684x over previous
#include <cuda_runtime.h>
#include <math.h>
#include <cfloat>
#include <stdint.h>

#define T_TOK 2048
#define HID   2048
#define NE_OLD 128
#define NE     48
#define TOPK   8
#define INTER  768
#define CAPCT  768

// ---------------- scratch (device globals; no allocation allowed) ----------
__device__ float d_logits[T_TOK * NE_OLD];
__device__ int   d_counts[NE];
__device__ int   d_slot_token[NE * CAPCT];
__device__ int   d_sel_idx[T_TOK * TOPK];
__device__ float d_sel_w[T_TOK * TOPK];
__device__ float d_hbuf[(size_t)NE * CAPCT * INTER];   // 113 MB
__device__ float d_ybuf[(size_t)NE * CAPCT * HID];     // 302 MB

// ======================= helpers (plain sm_103-legal) ======================
__device__ __forceinline__ uint32_t f2tf32(float f) {
    uint32_t r;
    asm("cvt.rna.tf32.f32 %0, %1;" : "=r"(r) : "f"(f));
    return r;
}
__device__ __forceinline__ void mma_tf32(float* c, const uint32_t* a, const uint32_t* b) {
    asm volatile(
        "mma.sync.aligned.m16n8k8.row.col.f32.tf32.tf32.f32 "
        "{%0,%1,%2,%3}, {%4,%5,%6,%7}, {%8,%9}, {%0,%1,%2,%3};"
        : "+f"(c[0]), "+f"(c[1]), "+f"(c[2]), "+f"(c[3])
        : "r"(a[0]), "r"(a[1]), "r"(a[2]), "r"(a[3]), "r"(b[0]), "r"(b[1]));
}
__device__ __forceinline__ uint32_t smem_u32(const void* p) {
    uint32_t a;
    asm("{ .reg .u64 t; cvta.to.shared.u64 t, %1; cvt.u32.u64 %0, t; }" : "=r"(a) : "l"(p));
    return a;
}
__device__ __forceinline__ void cp16(uint32_t s, const void* g) {
    asm volatile("cp.async.ca.shared.global [%0], [%1], 16;" :: "r"(s), "l"(g));
}
#define CP_COMMIT() asm volatile("cp.async.commit_group;" ::: "memory")
#define CP_WAIT0()  asm volatile("cp.async.wait_group 0;" ::: "memory")

#define KC 32                     // K chunk per stage
#define SPAD 36                   // 32 + 4 pad floats: frag LDS conflict-free
#define TSTAGE (128 * SPAD * 4)   // bytes per tile stage (18432)
#define SMEM_BYTES (4 * TSTAGE)   // As[2] + Bs[2] = 73728

// ---------------- 1) gating logits (fp32 exact — selection must be stable) -
__global__ void __launch_bounds__(256) gating_kernel(const float* __restrict__ x,
                                                     const float* __restrict__ gw)
{
    __shared__ float Xs[32][33];
    __shared__ float Gs[32][33];
    int tid = threadIdx.x;
    if (blockIdx.x == 0 && blockIdx.y == 0 && tid < NE) d_counts[tid] = 0;

    int t0 = blockIdx.x * 32;
    int e0 = blockIdx.y * 32;
    int ty = tid / 16, tx = tid % 16;
    int lr = tid >> 3;
    int lk = (tid & 7) * 4;

    float acc00 = 0.f, acc01 = 0.f, acc10 = 0.f, acc11 = 0.f;

    for (int k0 = 0; k0 < HID; k0 += 32) {
        float4 xv = *(const float4*)&x[(size_t)(t0 + lr) * HID + k0 + lk];
        float4 gv = *(const float4*)&gw[(size_t)(e0 + lr) * HID + k0 + lk];
        __syncthreads();
        Xs[lk + 0][lr] = xv.x; Xs[lk + 1][lr] = xv.y; Xs[lk + 2][lr] = xv.z; Xs[lk + 3][lr] = xv.w;
        Gs[lk + 0][lr] = gv.x; Gs[lk + 1][lr] = gv.y; Gs[lk + 2][lr] = gv.z; Gs[lk + 3][lr] = gv.w;
        __syncthreads();
#pragma unroll
        for (int k = 0; k < 32; k++) {
            float a0 = Xs[k][ty * 2], a1 = Xs[k][ty * 2 + 1];
            float b0 = Gs[k][tx * 2], b1 = Gs[k][tx * 2 + 1];
            acc00 += a0 * b0; acc01 += a0 * b1;
            acc10 += a1 * b0; acc11 += a1 * b1;
        }
    }
    int t = t0 + ty * 2, e = e0 + tx * 2;
    d_logits[(size_t)(t + 0) * NE_OLD + e + 0] = acc00;
    d_logits[(size_t)(t + 0) * NE_OLD + e + 1] = acc01;
    d_logits[(size_t)(t + 1) * NE_OLD + e + 0] = acc10;
    d_logits[(size_t)(t + 1) * NE_OLD + e + 1] = acc11;
}

// ---------------- 2) routing ----------------------------------------------
__global__ void __launch_bounds__(256) routing_kernel(const int* __restrict__ o2n)
{
    int warp = threadIdx.x >> 5;
    int lane = threadIdx.x & 31;
    int token = blockIdx.x * 8 + warp;

    float v[4];
#pragma unroll
    for (int j = 0; j < 4; j++) {
        int ee = lane + j * 32;
        float lv = d_logits[(size_t)token * NE_OLD + ee];
        v[j] = (o2n[ee] >= 0) ? lv : -FLT_MAX;
    }

    float topv[TOPK];
    int   tope[TOPK];
#pragma unroll
    for (int it = 0; it < TOPK; it++) {
        float bv = v[0]; int be = lane;
#pragma unroll
        for (int j = 1; j < 4; j++) {
            int ee = lane + j * 32;
            if (v[j] > bv || (v[j] == bv && ee < be)) { bv = v[j]; be = ee; }
        }
#pragma unroll
        for (int off = 16; off; off >>= 1) {
            float ov = __shfl_xor_sync(0xffffffffu, bv, off);
            int   oe = __shfl_xor_sync(0xffffffffu, be, off);
            if (ov > bv || (ov == bv && oe < be)) { bv = ov; be = oe; }
        }
        topv[it] = bv; tope[it] = be;
        int wj = be >> 5;
#pragma unroll
        for (int j = 0; j < 4; j++)
            if (wj == j && (be & 31) == lane) v[j] = -FLT_MAX;
    }

    float m = topv[0];
    float w[TOPK];
    float s = 0.f;
#pragma unroll
    for (int i = 0; i < TOPK; i++) { w[i] = expf(topv[i] - m); s += w[i]; }
    float inv = 1.f / s;

    if (lane < TOPK) {
        int i = lane;
        float wi = 0.f;
        int enew = 0;
#pragma unroll
        for (int j = 0; j < TOPK; j++) if (j == i) { wi = w[j] * inv; enew = o2n[tope[j]]; }
        int pos = atomicAdd(&d_counts[enew], 1);
        int sidx = 0; float sw = 0.f;
        if (pos < CAPCT) {
            d_slot_token[enew * CAPCT + pos] = token;
            sidx = enew * CAPCT + pos;
            sw = wi;
        }
        d_sel_idx[token * TOPK + i] = sidx;
        d_sel_w[token * TOPK + i] = sw;
    }
}

// ---------------- 3) GEMM1 (tf32 mma.sync, cp.async 2-stage) + SiLU --------
// Block tile: M=128 x 128 concat cols (16-row g/u interleave per warp).
// 8 warps 2(M) x 4(N); warp tile 64x32 of m16n8k8. SiLU fused in registers.
__global__ void __launch_bounds__(256) gemm1_mma(const float* __restrict__ x,
                                                 const float* __restrict__ gup)
{
    extern __shared__ char smem[];
    __shared__ int toks[128];
    const uint32_t sb = smem_u32(smem);

    int e = blockIdx.z;
    int cnt = min(d_counts[e], CAPCT);
    int m0 = blockIdx.y * 128;
    if (m0 >= cnt) return;
    int n0 = blockIdx.x * 64;
    int tid = threadIdx.x;
    int wid = tid >> 5, lane = tid & 31;
    int wm = wid >> 2, wn = wid & 3;
    int g = lane >> 2, q = lane & 3;

    if (tid < 128) {
        int m = m0 + tid;
        toks[tid] = d_slot_token[e * CAPCT + ((m < cnt) ? m : 0)];
    }
    __syncthreads();

    // loader mapping: 1024 float4 per tile, 4 per thread
    int arow[4], aqf[4];
    const float* bsrc[4];
    const float* asrc[4];
    uint32_t soff[4];
#pragma unroll
    for (int j = 0; j < 4; j++) {
        int idx = tid + j * 256;
        arow[j] = idx >> 3;
        aqf[j]  = (idx & 7) * 4;
        soff[j] = (uint32_t)(arow[j] * SPAD + aqf[j]) * 4u;
        int r = arow[j];
        int w = r >> 5, l = r & 31;
        int grow = (l < 16) ? (n0 + w * 16 + l) : (768 + n0 + w * 16 + (l - 16));
        bsrc[j] = gup + (size_t)e * 1536 * HID + (size_t)grow * HID + aqf[j];
        asrc[j] = x + (size_t)toks[arow[j]] * HID + aqf[j];
    }

    float acc[4][4][4];
#pragma unroll
    for (int i = 0; i < 4; i++)
#pragma unroll
        for (int jn = 0; jn < 4; jn++)
#pragma unroll
            for (int c = 0; c < 4; c++) acc[i][jn][c] = 0.f;

    const int NCH = HID / KC;   // 64
    // prologue: stage 0
#pragma unroll
    for (int j = 0; j < 4; j++) {
        cp16(sb + soff[j], asrc[j]);
        cp16(sb + 2 * TSTAGE + soff[j], bsrc[j]);
    }
    CP_COMMIT();

    for (int i = 0; i < NCH; i++) {
        int buf = i & 1;
        CP_WAIT0();
        __syncthreads();
        if (i + 1 < NCH) {
            int nb = buf ^ 1;
            int k1 = (i + 1) * KC;
#pragma unroll
            for (int j = 0; j < 4; j++) {
                cp16(sb + nb * TSTAGE + soff[j], asrc[j] + k1);
                cp16(sb + (2 + nb) * TSTAGE + soff[j], bsrc[j] + k1);
            }
            CP_COMMIT();
        }
        const float* Asb = (const float*)(smem + buf * TSTAGE);
        const float* Bsb = (const float*)(smem + (2 + buf) * TSTAGE);
#pragma unroll
        for (int kk = 0; kk < KC / 8; kk++) {
            int kb = kk * 8;
            uint32_t afrag[4][4], bfrag[4][2];
#pragma unroll
            for (int mf = 0; mf < 4; mf++) {
                int r = wm * 64 + mf * 16;
                afrag[mf][0] = f2tf32(Asb[(r + g    ) * SPAD + kb + q    ]);
                afrag[mf][1] = f2tf32(Asb[(r + g + 8) * SPAD + kb + q    ]);
                afrag[mf][2] = f2tf32(Asb[(r + g    ) * SPAD + kb + q + 4]);
                afrag[mf][3] = f2tf32(Asb[(r + g + 8) * SPAD + kb + q + 4]);
            }
#pragma unroll
            for (int nf = 0; nf < 4; nf++) {
                int r = wn * 32 + nf * 8 + g;
                bfrag[nf][0] = f2tf32(Bsb[r * SPAD + kb + q    ]);
                bfrag[nf][1] = f2tf32(Bsb[r * SPAD + kb + q + 4]);
            }
#pragma unroll
            for (int mf = 0; mf < 4; mf++)
#pragma unroll
                for (int nf = 0; nf < 4; nf++)
                    mma_tf32(acc[mf][nf], afrag[mf], bfrag[nf]);
        }
    }

    // epilogue: frags nf 0..1 = gate cols, nf+2 = matching up cols. SiLU in regs.
#pragma unroll
    for (int mf = 0; mf < 4; mf++) {
#pragma unroll
        for (int nf = 0; nf < 2; nf++) {
#pragma unroll
            for (int half = 0; half < 2; half++) {
                int m = m0 + wm * 64 + mf * 16 + g + half * 8;
                if (m < cnt) {
                    float g0 = acc[mf][nf][half * 2 + 0];
                    float g1 = acc[mf][nf][half * 2 + 1];
                    float u0 = acc[mf][nf + 2][half * 2 + 0];
                    float u1 = acc[mf][nf + 2][half * 2 + 1];
                    float2 h;
                    h.x = g0 / (1.f + __expf(-g0)) * u0;
                    h.y = g1 / (1.f + __expf(-g1)) * u1;
                    int col = n0 + 16 * wn + 8 * nf + 2 * q;
                    *(float2*)&d_hbuf[((size_t)e * CAPCT + m) * INTER + col] = h;
                }
            }
        }
    }
}

// ---------------- 4) GEMM2 (tf32 mma.sync, cp.async 2-stage) ---------------
// Block tile M=128 x N=128, K=768.
__global__ void __launch_bounds__(256) gemm2_mma(const float* __restrict__ down)
{
    extern __shared__ char smem[];
    const uint32_t sb = smem_u32(smem);

    int e = blockIdx.z;
    int cnt = min(d_counts[e], CAPCT);
    int m0 = blockIdx.y * 128;
    if (m0 >= cnt) return;
    int n0 = blockIdx.x * 128;
    int tid = threadIdx.x;
    int wid = tid >> 5, lane = tid & 31;
    int wm = wid >> 2, wn = wid & 3;
    int g = lane >> 2, q = lane & 3;

    const float* A = d_hbuf + ((size_t)e * CAPCT + m0) * INTER;
    const float* B = down + (size_t)e * HID * INTER + (size_t)n0 * INTER;

    int arow[4], aqf[4];
    uint32_t soff[4];
#pragma unroll
    for (int j = 0; j < 4; j++) {
        int idx = tid + j * 256;
        arow[j] = idx >> 3;
        aqf[j]  = (idx & 7) * 4;
        soff[j] = (uint32_t)(arow[j] * SPAD + aqf[j]) * 4u;
    }

    float acc[4][4][4];
#pragma unroll
    for (int i = 0; i < 4; i++)
#pragma unroll
        for (int jn = 0; jn < 4; jn++)
#pragma unroll
            for (int c = 0; c < 4; c++) acc[i][jn][c] = 0.f;

    const int NCH = INTER / KC;  // 24
#pragma unroll
    for (int j = 0; j < 4; j++) {
        cp16(sb + soff[j], &A[(size_t)arow[j] * INTER + aqf[j]]);
        cp16(sb + 2 * TSTAGE + soff[j], &B[(size_t)arow[j] * INTER + aqf[j]]);
    }
    CP_COMMIT();

    for (int i = 0; i < NCH; i++) {
        int buf = i & 1;
        CP_WAIT0();
        __syncthreads();
        if (i + 1 < NCH) {
            int nb = buf ^ 1;
            int k1 = (i + 1) * KC;
#pragma unroll
            for (int j = 0; j < 4; j++) {
                cp16(sb + nb * TSTAGE + soff[j], &A[(size_t)arow[j] * INTER + k1 + aqf[j]]);
                cp16(sb + (2 + nb) * TSTAGE + soff[j], &B[(size_t)arow[j] * INTER + k1 + aqf[j]]);
            }
            CP_COMMIT();
        }
        const float* Asb = (const float*)(smem + buf * TSTAGE);
        const float* Bsb = (const float*)(smem + (2 + buf) * TSTAGE);
#pragma unroll
        for (int kk = 0; kk < KC / 8; kk++) {
            int kb = kk * 8;
            uint32_t afrag[4][4], bfrag[4][2];
#pragma unroll
            for (int mf = 0; mf < 4; mf++) {
                int r = wm * 64 + mf * 16;
                afrag[mf][0] = f2tf32(Asb[(r + g    ) * SPAD + kb + q    ]);
                afrag[mf][1] = f2tf32(Asb[(r + g + 8) * SPAD + kb + q    ]);
                afrag[mf][2] = f2tf32(Asb[(r + g    ) * SPAD + kb + q + 4]);
                afrag[mf][3] = f2tf32(Asb[(r + g + 8) * SPAD + kb + q + 4]);
            }
#pragma unroll
            for (int nf = 0; nf < 4; nf++) {
                int r = wn * 32 + nf * 8 + g;
                bfrag[nf][0] = f2tf32(Bsb[r * SPAD + kb + q    ]);
                bfrag[nf][1] = f2tf32(Bsb[r * SPAD + kb + q + 4]);
            }
#pragma unroll
            for (int mf = 0; mf < 4; mf++)
#pragma unroll
                for (int nf = 0; nf < 4; nf++)
                    mma_tf32(acc[mf][nf], afrag[mf], bfrag[nf]);
        }
    }

#pragma unroll
    for (int mf = 0; mf < 4; mf++) {
#pragma unroll
        for (int nf = 0; nf < 4; nf++) {
#pragma unroll
            for (int half = 0; half < 2; half++) {
                int m = m0 + wm * 64 + mf * 16 + g + half * 8;
                if (m < cnt) {
                    float2 yv;
                    yv.x = acc[mf][nf][half * 2 + 0];
                    yv.y = acc[mf][nf][half * 2 + 1];
                    int col = n0 + 32 * wn + 8 * nf + 2 * q;
                    *(float2*)&d_ybuf[((size_t)e * CAPCT + m) * HID + col] = yv;
                }
            }
        }
    }
}

// ---------------- 5) combine ----------------------------------------------
__global__ void __launch_bounds__(256) gather_kernel(float* __restrict__ out)
{
    int t = blockIdx.x;
    __shared__ int  sidx[TOPK];
    __shared__ float sw[TOPK];
    if (threadIdx.x < TOPK) {
        sidx[threadIdx.x] = d_sel_idx[t * TOPK + threadIdx.x];
        sw[threadIdx.x]   = d_sel_w[t * TOPK + threadIdx.x];
    }
    __syncthreads();

    const float4* yb = (const float4*)d_ybuf;
    float4* o = (float4*)(out + (size_t)t * HID);
#pragma unroll
    for (int v = threadIdx.x; v < HID / 4; v += 256) {
        float4 acc = {0.f, 0.f, 0.f, 0.f};
#pragma unroll
        for (int k = 0; k < TOPK; k++) {
            float4 yv = yb[(size_t)sidx[k] * (HID / 4) + v];
            float wk = sw[k];
            acc.x += wk * yv.x; acc.y += wk * yv.y;
            acc.z += wk * yv.z; acc.w += wk * yv.w;
        }
        o[v] = acc;
    }
}

// ---------------- launch ---------------------------------------------------
extern "C" void kernel_launch(void* const* d_in, const int* in_sizes, int n_in,
                              void* d_out, int out_size)
{
    const float* x    = (const float*)d_in[0];   // hidden_states [2,1024,2048]
    const float* gw   = (const float*)d_in[1];   // gate_weight [128,2048]
    const float* gup  = (const float*)d_in[2];   // gate_up_proj [48,1536,2048]
    const float* down = (const float*)d_in[3];   // down_proj [48,2048,768]
    const int*   o2n  = (const int*)d_in[4];     // old_to_new [128]

    static int smem_set = 0;
    if (!smem_set) {
        cudaFuncSetAttribute(gemm1_mma, cudaFuncAttributeMaxDynamicSharedMemorySize, SMEM_BYTES);
        cudaFuncSetAttribute(gemm2_mma, cudaFuncAttributeMaxDynamicSharedMemorySize, SMEM_BYTES);
        smem_set = 1;
    }

    gating_kernel<<<dim3(T_TOK / 32, NE_OLD / 32), 256>>>(x, gw);
    routing_kernel<<<T_TOK / 8, 256>>>(o2n);
    gemm1_mma<<<dim3(INTER / 64, CAPCT / 128, NE), 256, SMEM_BYTES>>>(x, gup);
    gemm2_mma<<<dim3(HID / 128, CAPCT / 128, NE), 256, SMEM_BYTES>>>(down);
    gather_kernel<<<T_TOK, 256>>>((float*)d_out);
}